// round 1
// baseline (speedup 1.0000x reference)
#include <cuda_runtime.h>
#include <math.h>

#define BATCH 8
#define N     2048
#define RPC   32                 // rows per CTA in the big kernels
#define NBLK  (N / RPC)          // 64 row-blocks per batch
#define TPB   256
#define NITER 10

// scratch (no device allocation allowed; P0 lives in d_out)
__device__ float g_s[BATCH * N];
__device__ float g_t[BATCH * N];
__device__ float g_part[BATCH * NBLK * N];   // per-row-block column partial sums (4 MB)

template <bool IS_MAX>
__device__ __forceinline__ float block_reduce(float v, float* red, int tid) {
    __syncthreads();  // protect red[] reuse across calls
    #pragma unroll
    for (int o = 16; o; o >>= 1) {
        float other = __shfl_xor_sync(0xffffffffu, v, o);
        v = IS_MAX ? fmaxf(v, other) : (v + other);
    }
    if ((tid & 31) == 0) red[tid >> 5] = v;
    __syncthreads();
    if (tid < 32) {
        float w = (tid < (TPB / 32)) ? red[tid] : (IS_MAX ? -INFINITY : 0.0f);
        #pragma unroll
        for (int o = 4; o; o >>= 1) {
            float other = __shfl_xor_sync(0xffffffffu, w, o);
            w = IS_MAX ? fmaxf(w, other) : (w + other);
        }
        if (tid == 0) red[0] = w;
    }
    __syncthreads();
    return red[0];
}

// P0 = exp(A/lambda - rowmax)
__global__ void init_kernel(const float* __restrict__ A, float* __restrict__ P) {
    const int blk = blockIdx.x;
    const int b = blk / NBLK, rb = blk % NBLK;
    const int tid = threadIdx.x;
    const size_t base = (size_t)b * N * N;
    const int col = tid * 8;
    __shared__ float red[TPB / 32];
    #pragma unroll 1
    for (int r = 0; r < RPC; r++) {
        const int row = rb * RPC + r;
        const float4* ap = reinterpret_cast<const float4*>(A + base + (size_t)row * N + col);
        float4 a0 = ap[0], a1 = ap[1];
        float la[8] = {a0.x, a0.y, a0.z, a0.w, a1.x, a1.y, a1.z, a1.w};
        float m = -INFINITY;
        #pragma unroll
        for (int k = 0; k < 8; k++) { la[k] *= (1.0f / 0.05f); m = fmaxf(m, la[k]); }
        m = block_reduce<true>(m, red, tid);
        float4 o0, o1;
        o0.x = expf(la[0] - m); o0.y = expf(la[1] - m);
        o0.z = expf(la[2] - m); o0.w = expf(la[3] - m);
        o1.x = expf(la[4] - m); o1.y = expf(la[5] - m);
        o1.z = expf(la[6] - m); o1.w = expf(la[7] - m);
        float4* pp = reinterpret_cast<float4*>(P + base + (size_t)row * N + col);
        pp[0] = o0; pp[1] = o1;
    }
}

__global__ void set_t_kernel() {
    g_t[blockIdx.x * TPB + threadIdx.x] = 1.0f;
}

// one Sinkhorn iteration, single pass over P0:
//   s_i = 1/sum_j P0_ij * t_j ; per-CTA partials of sum_i P0_ij * s_i
__global__ void iter_kernel(const float* __restrict__ P) {
    const int blk = blockIdx.x;
    const int b = blk / NBLK, rb = blk % NBLK;
    const int tid = threadIdx.x;
    const size_t base = (size_t)b * N * N;
    const int col = tid * 8;
    __shared__ float red[TPB / 32];

    const float4 t0 = *reinterpret_cast<const float4*>(g_t + b * N + col);
    const float4 t1 = *reinterpret_cast<const float4*>(g_t + b * N + col + 4);
    float tv[8] = {t0.x, t0.y, t0.z, t0.w, t1.x, t1.y, t1.z, t1.w};
    float cp[8] = {0, 0, 0, 0, 0, 0, 0, 0};

    #pragma unroll 1
    for (int r = 0; r < RPC; r++) {
        const int row = rb * RPC + r;
        const float4* pp = reinterpret_cast<const float4*>(P + base + (size_t)row * N + col);
        float4 p0 = pp[0], p1 = pp[1];
        float val[8] = {p0.x, p0.y, p0.z, p0.w, p1.x, p1.y, p1.z, p1.w};
        float loc = 0.0f;
        #pragma unroll
        for (int k = 0; k < 8; k++) loc = fmaf(val[k], tv[k], loc);
        const float rowsum = block_reduce<false>(loc, red, tid);
        const float s = 1.0f / rowsum;
        if (tid == 0) g_s[b * N + row] = s;
        #pragma unroll
        for (int k = 0; k < 8; k++) cp[k] = fmaf(val[k], s, cp[k]);
    }
    float* gp = g_part + (size_t)(b * NBLK + rb) * N + col;
    float4 c0 = {cp[0], cp[1], cp[2], cp[3]};
    float4 c1 = {cp[4], cp[5], cp[6], cp[7]};
    reinterpret_cast<float4*>(gp)[0] = c0;
    reinterpret_cast<float4*>(gp)[1] = c1;
}

// t_j = 1 / sum over row-blocks of the column partials
__global__ void reduce_t_kernel() {
    const int idx = blockIdx.x * TPB + threadIdx.x;   // 0 .. BATCH*N-1
    const int b = idx >> 11;
    const int j = idx & (N - 1);
    const float* p = g_part + (size_t)b * NBLK * N + j;
    float a0 = 0.f, a1 = 0.f, a2 = 0.f, a3 = 0.f;
    #pragma unroll
    for (int k = 0; k < NBLK; k += 4) {
        a0 += p[(size_t)(k + 0) * N];
        a1 += p[(size_t)(k + 1) * N];
        a2 += p[(size_t)(k + 2) * N];
        a3 += p[(size_t)(k + 3) * N];
    }
    g_t[idx] = 1.0f / ((a0 + a1) + (a2 + a3));
}

// out = P0 * s_i * t_j  (in place on d_out)
__global__ void final_kernel(float* __restrict__ P) {
    const int row_g = blockIdx.x;         // 0 .. BATCH*N-1
    const int b = row_g >> 11;
    const int tid = threadIdx.x;
    const int col = tid * 8;
    const float s = g_s[row_g];
    const float4 t0 = *reinterpret_cast<const float4*>(g_t + b * N + col);
    const float4 t1 = *reinterpret_cast<const float4*>(g_t + b * N + col + 4);
    float4* pp = reinterpret_cast<float4*>(P + (size_t)row_g * N + col);
    float4 p0 = pp[0], p1 = pp[1];
    p0.x *= s * t0.x; p0.y *= s * t0.y; p0.z *= s * t0.z; p0.w *= s * t0.w;
    p1.x *= s * t1.x; p1.y *= s * t1.y; p1.z *= s * t1.z; p1.w *= s * t1.w;
    pp[0] = p0; pp[1] = p1;
}

extern "C" void kernel_launch(void* const* d_in, const int* in_sizes, int n_in,
                              void* d_out, int out_size) {
    const float* A = (const float*)d_in[0];
    float* P = (float*)d_out;   // d_out doubles as P0 scratch; rewritten in place at the end

    init_kernel<<<BATCH * NBLK, TPB>>>(A, P);
    set_t_kernel<<<(BATCH * N) / TPB, TPB>>>();
    for (int it = 0; it < NITER; it++) {
        iter_kernel<<<BATCH * NBLK, TPB>>>(P);
        reduce_t_kernel<<<(BATCH * N) / TPB, TPB>>>();
    }
    final_kernel<<<BATCH * N, TPB>>>(P);
}

// round 3
// speedup vs baseline: 1.4208x; 1.4208x over previous
#include <cuda_runtime.h>
#include <cuda_fp16.h>
#include <math.h>

#define BATCH 8
#define N     2048
#define TPB   256
#define RPC   32                    // rows per CTA in big kernels
#define NBLK  (N / RPC)             // 64
#define GRID_BIG (BATCH * NBLK)     // 512
#define INVL  20.0f                 // 1/lambda
#define NITER 10

// scratch (__device__ globals; no allocation allowed)
__device__ __half g_P[(size_t)BATCH * N * N];    // 67 MB: Q = fp16(P0 * s2 * t1), L2-resident
__device__ float  g_m[BATCH * N];                // row maxes of A*INVL
__device__ float  g_s[BATCH * N];                // s^(10)
__device__ float  g_acc[NITER + 1][BATCH * N];   // column accumulators per iteration

__global__ void zero_kernel() {
    int idx = blockIdx.x * TPB + threadIdx.x;    // zero acc[1..10]
    (&g_acc[1][0])[idx] = 0.0f;
}

__device__ __forceinline__ void warp_red2(float& l0, float& l1) {
    #pragma unroll
    for (int o = 16; o; o >>= 1) {
        l0 += __shfl_xor_sync(0xffffffffu, l0, o);
        l1 += __shfl_xor_sync(0xffffffffu, l1, o);
    }
}

// K1 = iteration 1 (fp32 from A): m_i = rowmax; s1 = 1/rowsum(P0); acc1 = colsum(P0 s1)
__global__ void __launch_bounds__(TPB) k1_kernel(const float* __restrict__ A) {
    const int blk = blockIdx.x, b = blk / NBLK, rb = blk % NBLK;
    const int tid = threadIdx.x, wid = tid >> 5, lane = tid & 31;
    const int col = tid * 8;
    const size_t base = (size_t)b * N * N;
    __shared__ float redA[8][2], redB[8][2];
    float cp[8] = {0, 0, 0, 0, 0, 0, 0, 0};

    #pragma unroll 1
    for (int p = 0; p < RPC / 2; p++) {
        const int r0 = rb * RPC + 2 * p;
        const float4* a0p = (const float4*)(A + base + (size_t)r0 * N + col);
        const float4* a1p = (const float4*)(A + base + (size_t)(r0 + 1) * N + col);
        float4 x0 = a0p[0], x1 = a0p[1], y0 = a1p[0], y1 = a1p[1];
        float a0[8] = {x0.x, x0.y, x0.z, x0.w, x1.x, x1.y, x1.z, x1.w};
        float a1[8] = {y0.x, y0.y, y0.z, y0.w, y1.x, y1.y, y1.z, y1.w};
        float m0 = -INFINITY, m1 = -INFINITY;
        #pragma unroll
        for (int k = 0; k < 8; k++) {
            a0[k] *= INVL; a1[k] *= INVL;
            m0 = fmaxf(m0, a0[k]); m1 = fmaxf(m1, a1[k]);
        }
        #pragma unroll
        for (int o = 16; o; o >>= 1) {
            m0 = fmaxf(m0, __shfl_xor_sync(0xffffffffu, m0, o));
            m1 = fmaxf(m1, __shfl_xor_sync(0xffffffffu, m1, o));
        }
        if (lane == 0) { redA[wid][0] = m0; redA[wid][1] = m1; }
        __syncthreads();
        m0 = redA[0][0]; m1 = redA[0][1];
        #pragma unroll
        for (int w = 1; w < 8; w++) { m0 = fmaxf(m0, redA[w][0]); m1 = fmaxf(m1, redA[w][1]); }

        float e0[8], e1[8], l0 = 0.0f, l1 = 0.0f;
        #pragma unroll
        for (int k = 0; k < 8; k++) {
            e0[k] = __expf(a0[k] - m0); e1[k] = __expf(a1[k] - m1);
            l0 += e0[k]; l1 += e1[k];
        }
        warp_red2(l0, l1);
        if (lane == 0) { redB[wid][0] = l0; redB[wid][1] = l1; }
        __syncthreads();
        l0 = redB[0][0]; l1 = redB[0][1];
        #pragma unroll
        for (int w = 1; w < 8; w++) { l0 += redB[w][0]; l1 += redB[w][1]; }
        const float s0 = 1.0f / l0, s1 = 1.0f / l1;
        if (tid == 0) { g_m[b * N + r0] = m0; g_m[b * N + r0 + 1] = m1; }
        #pragma unroll
        for (int k = 0; k < 8; k++) {
            cp[k] = fmaf(e0[k], s0, cp[k]);
            cp[k] = fmaf(e1[k], s1, cp[k]);
        }
    }
    float* acc = &g_acc[1][b * N + col];
    #pragma unroll
    for (int k = 0; k < 8; k++) atomicAdd(acc + k, cp[k]);
}

// K2 = iteration 2 (fp32 from A) + write Q = fp16(P0 s2 t1); acc2 = colsum(Q)
__global__ void __launch_bounds__(TPB) k2_kernel(const float* __restrict__ A) {
    const int blk = blockIdx.x, b = blk / NBLK, rb = blk % NBLK;
    const int tid = threadIdx.x, wid = tid >> 5, lane = tid & 31;
    const int col = tid * 8;
    const size_t base = (size_t)b * N * N;
    __shared__ float red[2][8][2];

    const float* a1p = &g_acc[1][b * N + col];
    float tv[8], cp[8] = {0, 0, 0, 0, 0, 0, 0, 0};
    #pragma unroll
    for (int j = 0; j < 8; j++) tv[j] = 1.0f / a1p[j];

    #pragma unroll 1
    for (int p = 0; p < RPC / 2; p++) {
        const int r0 = rb * RPC + 2 * p;
        const float4* p0 = (const float4*)(A + base + (size_t)r0 * N + col);
        const float4* p1 = (const float4*)(A + base + (size_t)(r0 + 1) * N + col);
        float4 x0 = p0[0], x1 = p0[1], y0 = p1[0], y1 = p1[1];
        float a0[8] = {x0.x, x0.y, x0.z, x0.w, x1.x, x1.y, x1.z, x1.w};
        float a1[8] = {y0.x, y0.y, y0.z, y0.w, y1.x, y1.y, y1.z, y1.w};
        const float m0 = g_m[b * N + r0], m1 = g_m[b * N + r0 + 1];
        float e0[8], e1[8], l0 = 0.0f, l1 = 0.0f;
        #pragma unroll
        for (int k = 0; k < 8; k++) {
            e0[k] = __expf(fmaf(a0[k], INVL, -m0)) * tv[k];   // P0 * t1
            e1[k] = __expf(fmaf(a1[k], INVL, -m1)) * tv[k];
            l0 += e0[k]; l1 += e1[k];
        }
        warp_red2(l0, l1);
        if (lane == 0) { red[p & 1][wid][0] = l0; red[p & 1][wid][1] = l1; }
        __syncthreads();
        l0 = red[p & 1][0][0]; l1 = red[p & 1][0][1];
        #pragma unroll
        for (int w = 1; w < 8; w++) { l0 += red[p & 1][w][0]; l1 += red[p & 1][w][1]; }
        const float s0 = 1.0f / l0, s1 = 1.0f / l1;   // s2 rows

        float q0[8], q1[8];
        #pragma unroll
        for (int k = 0; k < 8; k++) {
            q0[k] = e0[k] * s0;  q1[k] = e1[k] * s1;   // Q entries (row sums == 1)
            cp[k] += q0[k] + q1[k];
        }
        uint4 w0, w1;
        __half2* h0 = reinterpret_cast<__half2*>(&w0);
        __half2* h1 = reinterpret_cast<__half2*>(&w1);
        #pragma unroll
        for (int j = 0; j < 4; j++) {
            h0[j] = __floats2half2_rn(q0[2 * j], q0[2 * j + 1]);
            h1[j] = __floats2half2_rn(q1[2 * j], q1[2 * j + 1]);
        }
        *(uint4*)(g_P + base + (size_t)r0 * N + col) = w0;
        *(uint4*)(g_P + base + (size_t)(r0 + 1) * N + col) = w1;
    }
    float* acc = &g_acc[2][b * N + col];
    #pragma unroll
    for (int k = 0; k < 8; k++) atomicAdd(acc + k, cp[k]);
}

// K3..K9 = iterations 3..9 on fp16 Q (L2-resident):
//   tau = 1/acc[k-1]; sigma_i = 1/sum_j Q tau; acc[k] = colsum(Q sigma)
__global__ void __launch_bounds__(TPB) iter_kernel(int k) {
    const int blk = blockIdx.x, b = blk / NBLK, rb = blk % NBLK;
    const int tid = threadIdx.x, wid = tid >> 5, lane = tid & 31;
    const int col = tid * 8;
    const size_t base = (size_t)b * N * N;
    __shared__ float red[2][8][2];

    const float* ap = &g_acc[k - 1][b * N + col];
    float tv[8], cp[8] = {0, 0, 0, 0, 0, 0, 0, 0};
    #pragma unroll
    for (int j = 0; j < 8; j++) tv[j] = 1.0f / ap[j];

    const int rbase = rb * RPC;
    uint4 q0 = *(const uint4*)(g_P + base + (size_t)rbase * N + col);
    uint4 q1 = *(const uint4*)(g_P + base + (size_t)(rbase + 1) * N + col);

    #pragma unroll 1
    for (int p = 0; p < RPC / 2; p++) {
        const int r0 = rbase + 2 * p;
        float v0[8], v1[8];
        {
            const __half2* h0 = reinterpret_cast<const __half2*>(&q0);
            const __half2* h1 = reinterpret_cast<const __half2*>(&q1);
            #pragma unroll
            for (int j = 0; j < 4; j++) {
                float2 f0 = __half22float2(h0[j]); v0[2 * j] = f0.x; v0[2 * j + 1] = f0.y;
                float2 f1 = __half22float2(h1[j]); v1[2 * j] = f1.x; v1[2 * j + 1] = f1.y;
            }
        }
        // prefetch next round before the barrier (MLP)
        uint4 n0, n1;
        if (p + 1 < RPC / 2) {
            n0 = *(const uint4*)(g_P + base + (size_t)(r0 + 2) * N + col);
            n1 = *(const uint4*)(g_P + base + (size_t)(r0 + 3) * N + col);
        }
        float l0 = 0.0f, l1 = 0.0f;
        #pragma unroll
        for (int j = 0; j < 8; j++) { l0 = fmaf(v0[j], tv[j], l0); l1 = fmaf(v1[j], tv[j], l1); }
        warp_red2(l0, l1);
        if (lane == 0) { red[p & 1][wid][0] = l0; red[p & 1][wid][1] = l1; }
        __syncthreads();
        l0 = red[p & 1][0][0]; l1 = red[p & 1][0][1];
        #pragma unroll
        for (int w = 1; w < 8; w++) { l0 += red[p & 1][w][0]; l1 += red[p & 1][w][1]; }
        const float s0 = 1.0f / l0, s1 = 1.0f / l1;
        #pragma unroll
        for (int j = 0; j < 8; j++) {
            cp[j] = fmaf(v0[j], s0, cp[j]);
            cp[j] = fmaf(v1[j], s1, cp[j]);
        }
        q0 = n0; q1 = n1;
    }
    float* acc = &g_acc[k][b * N + col];
    #pragma unroll
    for (int j = 0; j < 8; j++) atomicAdd(acc + j, cp[j]);
}

// K10 = iteration 10 in fp32 from A: t9 = 1/(acc1*acc9); s10 -> g_s; acc10 = colsum(P0 s10)
__global__ void __launch_bounds__(TPB) k10_kernel(const float* __restrict__ A) {
    const int blk = blockIdx.x, b = blk / NBLK, rb = blk % NBLK;
    const int tid = threadIdx.x, wid = tid >> 5, lane = tid & 31;
    const int col = tid * 8;
    const size_t base = (size_t)b * N * N;
    __shared__ float red[2][8][2];

    const float* a1p = &g_acc[1][b * N + col];
    const float* a9p = &g_acc[9][b * N + col];
    float tv[8], cp[8] = {0, 0, 0, 0, 0, 0, 0, 0};
    #pragma unroll
    for (int j = 0; j < 8; j++) tv[j] = 1.0f / (a1p[j] * a9p[j]);   // absolute t^(9)

    #pragma unroll 1
    for (int p = 0; p < RPC / 2; p++) {
        const int r0 = rb * RPC + 2 * p;
        const float4* p0 = (const float4*)(A + base + (size_t)r0 * N + col);
        const float4* p1 = (const float4*)(A + base + (size_t)(r0 + 1) * N + col);
        float4 x0 = p0[0], x1 = p0[1], y0 = p1[0], y1 = p1[1];
        float a0[8] = {x0.x, x0.y, x0.z, x0.w, x1.x, x1.y, x1.z, x1.w};
        float a1[8] = {y0.x, y0.y, y0.z, y0.w, y1.x, y1.y, y1.z, y1.w};
        const float m0 = g_m[b * N + r0], m1 = g_m[b * N + r0 + 1];
        float e0[8], e1[8], l0 = 0.0f, l1 = 0.0f;
        #pragma unroll
        for (int k = 0; k < 8; k++) {
            e0[k] = __expf(fmaf(a0[k], INVL, -m0));
            e1[k] = __expf(fmaf(a1[k], INVL, -m1));
            l0 = fmaf(e0[k], tv[k], l0); l1 = fmaf(e1[k], tv[k], l1);
        }
        warp_red2(l0, l1);
        if (lane == 0) { red[p & 1][wid][0] = l0; red[p & 1][wid][1] = l1; }
        __syncthreads();
        l0 = red[p & 1][0][0]; l1 = red[p & 1][0][1];
        #pragma unroll
        for (int w = 1; w < 8; w++) { l0 += red[p & 1][w][0]; l1 += red[p & 1][w][1]; }
        const float s0 = 1.0f / l0, s1 = 1.0f / l1;   // s^(10)
        if (tid == 0) { g_s[b * N + r0] = s0; g_s[b * N + r0 + 1] = s1; }
        #pragma unroll
        for (int k = 0; k < 8; k++) {
            cp[k] = fmaf(e0[k], s0, cp[k]);
            cp[k] = fmaf(e1[k], s1, cp[k]);
        }
    }
    float* acc = &g_acc[NITER][b * N + col];
    #pragma unroll
    for (int k = 0; k < 8; k++) atomicAdd(acc + k, cp[k]);
}

// K11: out = exp(A*INVL - m_i) * s10_i * t10_j,  t10 = 1/acc10  (all fp32)
__global__ void __launch_bounds__(TPB) final_kernel(const float* __restrict__ A,
                                                    float* __restrict__ out) {
    const int rbase = blockIdx.x * 8;
    const int b = rbase >> 11;
    const int col = threadIdx.x * 8;
    const float* accp = &g_acc[NITER][b * N + col];
    float tv[8];
    #pragma unroll
    for (int j = 0; j < 8; j++) tv[j] = 1.0f / accp[j];

    #pragma unroll 1
    for (int r = 0; r < 8; r++) {
        const int row = rbase + r;
        const float s = g_s[row];
        const float m = g_m[row];
        const size_t off = (size_t)row * N + col;
        float4 x0 = *(const float4*)(A + off);
        float4 x1 = *(const float4*)(A + off + 4);
        float a[8] = {x0.x, x0.y, x0.z, x0.w, x1.x, x1.y, x1.z, x1.w};
        float4 o0, o1;
        o0.x = __expf(fmaf(a[0], INVL, -m)) * s * tv[0];
        o0.y = __expf(fmaf(a[1], INVL, -m)) * s * tv[1];
        o0.z = __expf(fmaf(a[2], INVL, -m)) * s * tv[2];
        o0.w = __expf(fmaf(a[3], INVL, -m)) * s * tv[3];
        o1.x = __expf(fmaf(a[4], INVL, -m)) * s * tv[4];
        o1.y = __expf(fmaf(a[5], INVL, -m)) * s * tv[5];
        o1.z = __expf(fmaf(a[6], INVL, -m)) * s * tv[6];
        o1.w = __expf(fmaf(a[7], INVL, -m)) * s * tv[7];
        *(float4*)(out + off) = o0;
        *(float4*)(out + off + 4) = o1;
    }
}

extern "C" void kernel_launch(void* const* d_in, const int* in_sizes, int n_in,
                              void* d_out, int out_size) {
    const float* A = (const float*)d_in[0];
    float* O = (float*)d_out;

    zero_kernel<<<(NITER * BATCH * N) / TPB, TPB>>>();
    k1_kernel<<<GRID_BIG, TPB>>>(A);
    k2_kernel<<<GRID_BIG, TPB>>>(A);
    for (int k = 3; k <= NITER - 1; k++)
        iter_kernel<<<GRID_BIG, TPB>>>(k);
    k10_kernel<<<GRID_BIG, TPB>>>(A);
    final_kernel<<<(BATCH * N) / 8, TPB>>>(A, O);
}